// round 16
// baseline (speedup 1.0000x reference)
#include <cuda_runtime.h>
#include <cuda_fp16.h>
#include <cstdint>

#define T_STEPS 20
#define N_NODES 32768
#define TILE_N  64
#define DH      128
#define NBLOCKS (N_NODES / TILE_N)   // 512
#define NTHREADS 128                 // 4 warps; warp w owns rows w*16..w*16+15
#define NCHUNKS 16                   // gate-col chunks (32 interleaved rows each)
#define XPITCH  400                  // bytes per X row (200 fp16)
#define HLPITCH 256                  // bytes per h-lo shadow row (128 fp16)
#define WCHUNK  12288                // full chunk bytes: 12*2*32*16
#define WBUF    12288

// SMEM byte offsets (total 104736 -> 2 CTAs/SM)
#define SM_XH 0                      // 64 x 400 = 25600
#define SM_HL 25600                  // h lo shadow: 64 x 256 = 16384 (not used by MMA)
#define SM_WB 41984                  // 2 x WBUF = 24576
#define SM_C  66560                  // staged c: [mt][nc][nh][q][lane] = 8192 f32 = 32768
#define SM_F  99328                  // 1352 floats = 5408
#define SMEM_TOTAL 104736

// ---- static device scratch ----
// W fp16 fragments: [nc(16)][kh(2)][kk6(6)][nh(2)][lane(32)] uint4; one nc = 12288B contiguous
__device__ uint4 g_WF[32 * 6 * 2 * 32];

__global__ void prep_frag(const float* __restrict__ Wih, const float* __restrict__ Whh) {
    int idx = blockIdx.x * blockDim.x + threadIdx.x;   // 49152 uint32 words
    if (idx >= 32 * 6 * 2 * 32 * 4) return;
    int r    = idx & 3;
    int lane = (idx >> 2) & 31;
    int nh   = (idx >> 7) & 1;
    int tmp  = idx >> 8;          // [nc(16)][kh(2)][kk6(6)]
    int kk6  = tmp % 6;
    int kh   = (tmp / 6) & 1;
    int nc   = tmp / 12;
    int q = r >> 1, rr = r & 1;
    int np = nc * 32 + nh * 16 + q * 8 + (lane >> 2);   // gate-interleaved row j*4+g
    int kk = kh * 6 + kk6;
    int k0 = kk * 16 + (lane & 3) * 2 + rr * 8;
    int col = (np & 3) * 128 + (np >> 2);               // g*128 + j
    float w0 = (k0 < 64) ? Wih[k0 * 512 + col] : Whh[(k0 - 64) * 512 + col];
    int k1 = k0 + 1;
    float w1 = (k1 < 64) ? Wih[k1 * 512 + col] : Whh[(k1 - 64) * 512 + col];
    unsigned short a = __half_as_ushort(__float2half_rn(w0));
    unsigned short b = __half_as_ushort(__float2half_rn(w1));
    int dw = ((((nc * 2 + kh) * 6 + kk6) * 2 + nh) * 32 + lane) * 4 + r;
    ((uint32_t*)g_WF)[dw] = (uint32_t)a | ((uint32_t)b << 16);
}

__device__ __forceinline__ uint32_t smem_u32(const void* p) {
    uint32_t a;
    asm("{ .reg .u64 t; cvta.to.shared.u64 t, %1; cvt.u32.u64 %0, t; }" : "=r"(a) : "l"(p));
    return a;
}
__device__ __forceinline__ void ldsm4(uint32_t& r0, uint32_t& r1, uint32_t& r2, uint32_t& r3, uint32_t addr) {
    asm volatile("ldmatrix.sync.aligned.m8n8.x4.shared.b16 {%0,%1,%2,%3}, [%4];"
                 : "=r"(r0), "=r"(r1), "=r"(r2), "=r"(r3) : "r"(addr));
}
__device__ __forceinline__ void mma16816h(float* d, const uint32_t* a, uint32_t b0, uint32_t b1) {
    asm volatile("mma.sync.aligned.m16n8k16.row.col.f32.f16.f16.f32 "
                 "{%0,%1,%2,%3},{%4,%5,%6,%7},{%8,%9},{%0,%1,%2,%3};"
                 : "+f"(d[0]), "+f"(d[1]), "+f"(d[2]), "+f"(d[3])
                 : "r"(a[0]), "r"(a[1]), "r"(a[2]), "r"(a[3]), "r"(b0), "r"(b1));
}
__device__ __forceinline__ void cpasync16(uint32_t dst, const void* src) {
    asm volatile("cp.async.cg.shared.global [%0], [%1], 16;" :: "r"(dst), "l"(src) : "memory");
}
#define CP_COMMIT() asm volatile("cp.async.commit_group;" ::: "memory")
#define CP_WAIT0()  asm volatile("cp.async.wait_group 0;" ::: "memory")

__device__ __forceinline__ float tanh_apx(float x) {
    float y;
    asm("tanh.approx.f32 %0, %1;" : "=f"(y) : "f"(x));
    return y;
}
__device__ __forceinline__ float sigm(float x) { return fmaf(0.5f, tanh_apx(0.5f * x), 0.5f); }
__device__ __forceinline__ void fp16_split(float v, unsigned short& hi, unsigned short& lo) {
    __half h = __float2half_rn(v);
    hi = __half_as_ushort(h);
    lo = __half_as_ushort(__float2half_rn(v - __half2float(h)));
}
// staged-c word index for logical (n, j), n in 0..63, j in 0..127
__device__ __forceinline__ int c_word(int n, int j) {
    int lane = ((n & 7) << 2) | ((j & 1) << 1) | ((n >> 3) & 1);
    return (n >> 4) * 2048 + (j >> 3) * 128 + ((j >> 2) & 1) * 64 + ((j >> 1) & 1) * 32 + lane;
}

__global__ __launch_bounds__(NTHREADS, 2)
void vlstm_mma(const float* __restrict__ nodes,
               const int* __restrict__ mask,
               const float* __restrict__ h0,
               const float* __restrict__ c0,
               const float* __restrict__ We,
               const float* __restrict__ be,
               const float* __restrict__ bih,
               const float* __restrict__ bhh,
               const float* __restrict__ Wout,
               const float* __restrict__ bout,
               float* __restrict__ out,
               float* __restrict__ hfin,
               float* __restrict__ cfin) {
    extern __shared__ char smem[];
    float* scf   = (float*)(smem + SM_C);
    float* sBias = (float*)(smem + SM_F);   // 512
    float* sWe   = sBias + 512;
    float* sBe   = sWe + 128;
    float* sWout = sBe + 64;
    float* sBout = sWout + 640;

    const int tid  = threadIdx.x;
    const int wid  = tid >> 5, lane = tid & 31;
    const int base = blockIdx.x * TILE_N;
    const uint32_t sbase = smem_u32(smem);

    for (int i = tid; i < 512; i += NTHREADS) sBias[i] = bih[i] + bhh[i];
    if (tid < 128) sWe[tid] = We[tid];
    if (tid < 64)  sBe[tid] = be[tid];
    for (int i = tid; i < 640; i += NTHREADS) sWout[i] = Wout[i];
    if (tid < 5) sBout[tid] = bout[tid];
    for (int idx = tid; idx < TILE_N * DH; idx += NTHREADS) {
        int n = idx >> 7, j = idx & 127;
        unsigned short hb, lb;
        fp16_split(h0[(size_t)(base + n) * DH + j], hb, lb);
        *(unsigned short*)(smem + SM_XH + n * XPITCH + 128 + 2 * j) = hb;
        *(unsigned short*)(smem + SM_HL + n * HLPITCH + 2 * j) = lb;
        scf[c_word(n, j)] = c0[(size_t)(base + n) * DH + j];
    }
    __syncthreads();

    const int mt = wid;                       // warp owns rows mt*16..mt*16+15
    const uint32_t aoff = (uint32_t)((lane & 7) + ((lane >> 3) & 1) * 8) * XPITCH
                        + (uint32_t)(lane >> 4) * 16;
    const uint32_t xhBase = sbase + SM_XH + (uint32_t)mt * 16 * XPITCH;
    const int p4 = lane & 3, odd = p4 & 1;
    const int jlsb = (lane >> 1) & 1;
    const int row = mt * 16 + (lane >> 2) + odd * 8;
    const int node = base + row;
    const int mtBase = mt * 2048;             // staged-c base word for this warp
    const int erow = mt * 16 + (lane >> 1);
    const int ekb  = (lane & 1) * 32;

    #define EPILOGUE(ACC, NCE)                                                       \
    {                                                                                \
        _Pragma("unroll")                                                            \
        for (int nh = 0; nh < 2; nh++) {                                             \
            _Pragma("unroll")                                                        \
            for (int q = 0; q < 2; q++) {                                            \
                float* d = (ACC) + (nh * 2 + q) * 4;                                 \
                float v0 = odd ? d[0] : d[2];                                        \
                float v1 = odd ? d[1] : d[3];                                        \
                float r0 = __shfl_xor_sync(0xffffffffu, v0, 1);                      \
                float r1 = __shfl_xor_sync(0xffffffffu, v1, 1);                      \
                float gi, gf, gg, go;                                                \
                if (!odd) { gi = d[0]; gf = d[1]; gg = r0; go = r1; }                 \
                else      { gi = r0;   gf = r1;   gg = d[2]; go = d[3]; }             \
                int j = (NCE) * 8 + nh * 4 + q * 2 + jlsb;                           \
                int scw = mtBase + (NCE) * 128 + nh * 64 + q * 32 + lane;            \
                float cold = scf[scw];                                               \
                float iv = sigm(gi + sBias[j]);                                      \
                float fv = sigm(gf + sBias[128 + j]);                                \
                float gv = tanh_apx(gg + sBias[256 + j]);                            \
                float ov = sigm(go + sBias[384 + j]);                                \
                float cn = fmaf(fv, cold, iv * gv);                                  \
                float hn = ov * tanh_apx(cn);                                        \
                scf[scw] = act ? cn : cold;                                          \
                float hg = act ? hn : 0.0f;                                          \
                unsigned short hb, lb;                                               \
                fp16_split(hn, hb, lb);                                              \
                uint32_t hbu = hb, lbu = lb;                                         \
                uint32_t phb = __shfl_xor_sync(0xffffffffu, hbu, 2);                 \
                uint32_t plb = __shfl_xor_sync(0xffffffffu, lbu, 2);                 \
                if (act && jlsb == 0) {                                              \
                    *(uint32_t*)(smem + SM_XH + row * XPITCH + 128 + 2 * j)          \
                        = hbu | (phb << 16);                                         \
                    *(uint32_t*)(smem + SM_HL + row * HLPITCH + 2 * j)               \
                        = lbu | (plb << 16);                                         \
                }                                                                    \
                const float* w0 = sWout + j * 5;                                     \
                oacc[0] = fmaf(hg, w0[0], oacc[0]);                                  \
                oacc[1] = fmaf(hg, w0[1], oacc[1]);                                  \
                oacc[2] = fmaf(hg, w0[2], oacc[2]);                                  \
                oacc[3] = fmaf(hg, w0[3], oacc[3]);                                  \
                oacc[4] = fmaf(hg, w0[4], oacc[4]);                                  \
            }                                                                        \
        }                                                                            \
    }

    // Full chunk (12 kk): 4 MMAs per kk over 4 acc chains, single-fp16 A.
    #define MMA_CHUNK(ACC, BUF)                                                      \
    {                                                                                \
        const char* wch = smem + SM_WB + (BUF) * WBUF;                               \
        _Pragma("unroll")                                                            \
        for (int z = 0; z < 16; z++) (ACC)[z] = 0.0f;                                \
        uint4 nh0 = *(const uint4*)(wch + lane * 16);                                \
        uint4 nh1 = *(const uint4*)(wch + 512 + lane * 16);                          \
        _Pragma("unroll")                                                            \
        for (int kk = 0; kk < 12; kk++) {                                            \
            uint4 ch0 = nh0, ch1 = nh1;                                              \
            if (kk < 11) {                                                           \
                int kn = kk + 1;                                                     \
                int o = (kn >= 6) * 6144 + (kn - (kn >= 6) * 6) * 1024 + lane * 16;  \
                nh0 = *(const uint4*)(wch + o);                                      \
                nh1 = *(const uint4*)(wch + o + 512);                                \
            }                                                                        \
            mma16816h((ACC) + 0,  AH[kk], ch0.x, ch0.y);                             \
            mma16816h((ACC) + 4,  AH[kk], ch0.z, ch0.w);                             \
            mma16816h((ACC) + 8,  AH[kk], ch1.x, ch1.y);                             \
            mma16816h((ACC) + 12, AH[kk], ch1.z, ch1.w);                             \
        }                                                                            \
    }

    // Prefetch full chunk NC (12288B) into buffer NC&1: 96B per thread
    #define PREFETCH_W(NC)                                                           \
    {                                                                                \
        uint32_t dst = sbase + SM_WB + ((NC) & 1) * WBUF;                            \
        const char* srcW = (const char*)g_WF + (NC) * WCHUNK;                        \
        _Pragma("unroll")                                                            \
        for (int i = 0; i < 6; i++) {                                                \
            int o = tid * 16 + i * 2048;                                             \
            cpasync16(dst + o, srcW + o);                                            \
        }                                                                            \
        CP_COMMIT();                                                                 \
    }

    for (int t = 0; t < T_STEPS; t++) {
        const int act = mask[(size_t)t * N_NODES + node];

        // emb rebuild (warp-private rows), packed fp16 stores
        {
            float2 xy = ((const float2*)nodes)[(size_t)t * N_NODES + base + erow];
            #pragma unroll 4
            for (int i = 0; i < 16; i++) {
                int k = ekb + 2 * i;
                float e0 = fmaxf(fmaf(xy.x, sWe[k], fmaf(xy.y, sWe[64 + k], sBe[k])), 0.0f);
                float e1 = fmaxf(fmaf(xy.x, sWe[k + 1], fmaf(xy.y, sWe[64 + k + 1], sBe[k + 1])), 0.0f);
                uint32_t pk = (uint32_t)__half_as_ushort(__float2half_rn(e0))
                            | ((uint32_t)__half_as_ushort(__float2half_rn(e1)) << 16);
                *(uint32_t*)(smem + SM_XH + erow * XPITCH + 2 * k) = pk;
            }
        }
        __syncwarp();

        PREFETCH_W(0)

        // load A fragments once per step (register-resident X, single fp16)
        uint32_t AH[12][4];
        #pragma unroll
        for (int kk = 0; kk < 12; kk++)
            ldsm4(AH[kk][0], AH[kk][1], AH[kk][2], AH[kk][3], xhBase + aoff + kk * 32);

        float oacc[5] = {0.f, 0.f, 0.f, 0.f, 0.f};
        float accA[16], accB[16];

        // pipelined chunk loop: 1 barrier per chunk, epilogue(nc-1) under MMA(nc)
        for (int nc2 = 0; nc2 < NCHUNKS; nc2 += 2) {
            CP_WAIT0();
            __syncthreads();
            if (nc2 + 1 < NCHUNKS) PREFETCH_W(nc2 + 1)
            MMA_CHUNK(accA, 0)
            if (nc2 > 0) EPILOGUE(accB, nc2 - 1)
            CP_WAIT0();
            __syncthreads();
            if (nc2 + 2 < NCHUNKS) PREFETCH_W(nc2 + 2)
            MMA_CHUNK(accB, 1)
            EPILOGUE(accA, nc2)
        }
        EPILOGUE(accB, NCHUNKS - 1)

        // combine j-halves and write out
        float comb[5];
        #pragma unroll
        for (int z = 0; z < 5; z++)
            comb[z] = oacc[z] + __shfl_xor_sync(0xffffffffu, oacc[z], 2);
        if (p4 < 2) {
            float* op = out + ((size_t)t * N_NODES + node) * 5;
            if (act) {
                op[0] = comb[0] + sBout[0];
                op[1] = comb[1] + sBout[1];
                op[2] = comb[2] + sBout[2];
                op[3] = comb[3] + sBout[3];
                op[4] = comb[4] + sBout[4];
            } else {
                op[0] = 0.f; op[1] = 0.f; op[2] = 0.f; op[3] = 0.f; op[4] = 0.f;
            }
        }
    }

    // ---- final h (exact hi+lo reconstruction), c ----
    __syncthreads();
    for (int idx = tid; idx < TILE_N * DH; idx += NTHREADS) {
        int n = idx >> 7, j = idx & 127;
        float hv = __half2float(__ushort_as_half(
                       *(unsigned short*)(smem + SM_XH + n * XPITCH + 128 + 2 * j)))
                 + __half2float(__ushort_as_half(
                       *(unsigned short*)(smem + SM_HL + n * HLPITCH + 2 * j)));
        hfin[(size_t)(base + n) * DH + j] = hv;
        cfin[(size_t)(base + n) * DH + j] = scf[c_word(n, j)];
    }
}

extern "C" void kernel_launch(void* const* d_in, const int* in_sizes, int n_in,
                              void* d_out, int out_size) {
    const float* nodes = (const float*)d_in[0];
    const int* mask    = (const int*)d_in[1];
    const float* h0    = (const float*)d_in[2];
    const float* c0    = (const float*)d_in[3];
    const float* We    = (const float*)d_in[4];
    const float* be    = (const float*)d_in[5];
    const float* Wih   = (const float*)d_in[6];
    const float* bih   = (const float*)d_in[7];
    const float* Whh   = (const float*)d_in[8];
    const float* bhh   = (const float*)d_in[9];
    const float* Wout  = (const float*)d_in[10];
    const float* bout  = (const float*)d_in[11];

    float* out  = (float*)d_out;
    float* hfin = out + (size_t)T_STEPS * N_NODES * 5;
    float* cfin = hfin + (size_t)N_NODES * DH;

    prep_frag<<<(32 * 6 * 2 * 32 * 4 + 255) / 256, 256>>>(Wih, Whh);

    cudaFuncSetAttribute(vlstm_mma, cudaFuncAttributeMaxDynamicSharedMemorySize, SMEM_TOTAL);
    vlstm_mma<<<NBLOCKS, NTHREADS, SMEM_TOTAL>>>(
        nodes, mask, h0, c0, We, be, bih, bhh, Wout, bout, out, hfin, cfin);
}

// round 17
// speedup vs baseline: 1.1083x; 1.1083x over previous
#include <cuda_runtime.h>
#include <cuda_fp16.h>
#include <cstdint>

#define T_STEPS 20
#define N_NODES 32768
#define TILE_N  64
#define DH      128
#define NBLOCKS (N_NODES / TILE_N)   // 512
#define NTHREADS 256                 // 8 warps; pair (g,p): rows g*16..+15, chunk parity p
#define NCHUNKS 16
#define XPITCH  400                  // bytes per X row (200 fp16)
#define CPITCH  129
#define WCHUNK  12288                // one chunk of W frags
#define WPAIR   24576                // chunk pair

// SMEM byte offsets (total 114944 -> target 2 CTAs/SM)
#define SM_XH 0                      // 64 x 400 = 25600
#define SM_WB 25600                  // 2 pair-buffers x 24576 = 49152
#define SM_C  74752                  // 64 x 129 x 4 = 33024
#define SM_F  107776                 // sBias 512 + sWout 640 + sOutP 640 = 1792 floats
#define SMEM_TOTAL 114944

// ---- static device scratch ----
__device__ uint4 g_WF[32 * 6 * 2 * 32];                   // fp16 W fragments (16 chunks x 12288B)
__device__ unsigned short g_HL[(size_t)N_NODES * DH];     // h lo shadow (write-only in loop)

__global__ void prep_frag(const float* __restrict__ Wih, const float* __restrict__ Whh) {
    int idx = blockIdx.x * blockDim.x + threadIdx.x;   // 49152 uint32 words
    if (idx >= 32 * 6 * 2 * 32 * 4) return;
    int r    = idx & 3;
    int lane = (idx >> 2) & 31;
    int nh   = (idx >> 7) & 1;
    int tmp  = idx >> 8;          // [nc(16)][kh(2)][kk6(6)]
    int kk6  = tmp % 6;
    int kh   = (tmp / 6) & 1;
    int nc   = tmp / 12;
    int q = r >> 1, rr = r & 1;
    int np = nc * 32 + nh * 16 + q * 8 + (lane >> 2);   // gate-interleaved row j*4+g
    int kk = kh * 6 + kk6;
    int k0 = kk * 16 + (lane & 3) * 2 + rr * 8;
    int col = (np & 3) * 128 + (np >> 2);               // g*128 + j
    float w0 = (k0 < 64) ? Wih[k0 * 512 + col] : Whh[(k0 - 64) * 512 + col];
    int k1 = k0 + 1;
    float w1 = (k1 < 64) ? Wih[k1 * 512 + col] : Whh[(k1 - 64) * 512 + col];
    unsigned short a = __half_as_ushort(__float2half_rn(w0));
    unsigned short b = __half_as_ushort(__float2half_rn(w1));
    int dw = ((((nc * 2 + kh) * 6 + kk6) * 2 + nh) * 32 + lane) * 4 + r;
    ((uint32_t*)g_WF)[dw] = (uint32_t)a | ((uint32_t)b << 16);
}

__device__ __forceinline__ uint32_t smem_u32(const void* p) {
    uint32_t a;
    asm("{ .reg .u64 t; cvta.to.shared.u64 t, %1; cvt.u32.u64 %0, t; }" : "=r"(a) : "l"(p));
    return a;
}
__device__ __forceinline__ void ldsm4(uint32_t& r0, uint32_t& r1, uint32_t& r2, uint32_t& r3, uint32_t addr) {
    asm volatile("ldmatrix.sync.aligned.m8n8.x4.shared.b16 {%0,%1,%2,%3}, [%4];"
                 : "=r"(r0), "=r"(r1), "=r"(r2), "=r"(r3) : "r"(addr));
}
__device__ __forceinline__ void mma16816h(float* d, const uint32_t* a, uint32_t b0, uint32_t b1) {
    asm volatile("mma.sync.aligned.m16n8k16.row.col.f32.f16.f16.f32 "
                 "{%0,%1,%2,%3},{%4,%5,%6,%7},{%8,%9},{%0,%1,%2,%3};"
                 : "+f"(d[0]), "+f"(d[1]), "+f"(d[2]), "+f"(d[3])
                 : "r"(a[0]), "r"(a[1]), "r"(a[2]), "r"(a[3]), "r"(b0), "r"(b1));
}
__device__ __forceinline__ void cpasync16(uint32_t dst, const void* src) {
    asm volatile("cp.async.cg.shared.global [%0], [%1], 16;" :: "r"(dst), "l"(src) : "memory");
}
#define CP_COMMIT() asm volatile("cp.async.commit_group;" ::: "memory")
#define CP_WAIT0()  asm volatile("cp.async.wait_group 0;" ::: "memory")

__device__ __forceinline__ float tanh_apx(float x) {
    float y;
    asm("tanh.approx.f32 %0, %1;" : "=f"(y) : "f"(x));
    return y;
}
__device__ __forceinline__ float sigm(float x) { return fmaf(0.5f, tanh_apx(0.5f * x), 0.5f); }
__device__ __forceinline__ void fp16_split(float v, unsigned short& hi, unsigned short& lo) {
    __half h = __float2half_rn(v);
    hi = __half_as_ushort(h);
    lo = __half_as_ushort(__float2half_rn(v - __half2float(h)));
}

__global__ __launch_bounds__(NTHREADS, 2)
void vlstm_mma(const float* __restrict__ nodes,
               const int* __restrict__ mask,
               const float* __restrict__ h0,
               const float* __restrict__ c0,
               const float* __restrict__ We,
               const float* __restrict__ be,
               const float* __restrict__ bih,
               const float* __restrict__ bhh,
               const float* __restrict__ Wout,
               const float* __restrict__ bout,
               float* __restrict__ out,
               float* __restrict__ hfin,
               float* __restrict__ cfin) {
    extern __shared__ char smem[];
    float* sc    = (float*)(smem + SM_C);
    float* sBias = (float*)(smem + SM_F);   // 512
    float* sWout = sBias + 512;             // 640
    float* sOutP = sWout + 640;             // 64 x 2 x 5

    const int tid  = threadIdx.x;
    const int wid  = tid >> 5, lane = tid & 31;
    const int base = blockIdx.x * TILE_N;
    const uint32_t sbase = smem_u32(smem);

    for (int i = tid; i < 512; i += NTHREADS) sBias[i] = bih[i] + bhh[i];
    for (int i = tid; i < 640; i += NTHREADS) sWout[i] = Wout[i];
    for (int idx = tid; idx < TILE_N * DH; idx += NTHREADS) {
        int n = idx >> 7, j = idx & 127;
        unsigned short hb, lb;
        fp16_split(h0[(size_t)(base + n) * DH + j], hb, lb);
        *(unsigned short*)(smem + SM_XH + n * XPITCH + 128 + 2 * j) = hb;
        g_HL[(size_t)(base + n) * DH + j] = lb;
        sc[n * CPITCH + j] = c0[(size_t)(base + n) * DH + j];
    }
    __syncthreads();

    const int mt  = wid >> 1;                 // row group: rows mt*16..mt*16+15
    const int par = wid & 1;                  // chunk parity
    const uint32_t aoff = (uint32_t)((lane & 7) + ((lane >> 3) & 1) * 8) * XPITCH
                        + (uint32_t)(lane >> 4) * 16;
    const uint32_t xhBase = sbase + SM_XH + (uint32_t)mt * 16 * XPITCH;
    const int p4 = lane & 3, odd = p4 & 1;
    const int jlsb = (lane >> 1) & 1;
    const int row = mt * 16 + (lane >> 2) + odd * 8;
    const int node = base + row;
    const int erow = mt * 16 + (lane >> 1);
    const int ek0  = (lane & 1) * 32 + par * 16;   // 16 k's per lane (pair-split)

    #define EPILOGUE(ACC, NCE)                                                       \
    {                                                                                \
        _Pragma("unroll")                                                            \
        for (int nh = 0; nh < 2; nh++) {                                             \
            _Pragma("unroll")                                                        \
            for (int q = 0; q < 2; q++) {                                            \
                float* d = (ACC) + (nh * 2 + q) * 4;                                 \
                float v0 = odd ? d[0] : d[2];                                        \
                float v1 = odd ? d[1] : d[3];                                        \
                float r0 = __shfl_xor_sync(0xffffffffu, v0, 1);                      \
                float r1 = __shfl_xor_sync(0xffffffffu, v1, 1);                      \
                float gi, gf, gg, go;                                                \
                if (!odd) { gi = d[0]; gf = d[1]; gg = r0; go = r1; }                 \
                else      { gi = r0;   gf = r1;   gg = d[2]; go = d[3]; }             \
                int j = (NCE) * 8 + nh * 4 + q * 2 + jlsb;                           \
                float cold = sc[row * CPITCH + j];                                   \
                float iv = sigm(gi + sBias[j]);                                      \
                float fv = sigm(gf + sBias[128 + j]);                                \
                float gv = tanh_apx(gg + sBias[256 + j]);                            \
                float ov = sigm(go + sBias[384 + j]);                                \
                float cn = fmaf(fv, cold, iv * gv);                                  \
                float hn = ov * tanh_apx(cn);                                        \
                sc[row * CPITCH + j] = act ? cn : cold;                              \
                float hg = act ? hn : 0.0f;                                          \
                if (act) {                                                           \
                    unsigned short hb, lb;                                           \
                    fp16_split(hn, hb, lb);                                          \
                    *(unsigned short*)(smem + SM_XH + row * XPITCH + 128 + 2 * j) = hb; \
                    g_HL[(size_t)node * DH + j] = lb;                                \
                }                                                                    \
                const float* w0 = sWout + j * 5;                                     \
                oacc[0] = fmaf(hg, w0[0], oacc[0]);                                  \
                oacc[1] = fmaf(hg, w0[1], oacc[1]);                                  \
                oacc[2] = fmaf(hg, w0[2], oacc[2]);                                  \
                oacc[3] = fmaf(hg, w0[3], oacc[3]);                                  \
                oacc[4] = fmaf(hg, w0[4], oacc[4]);                                  \
            }                                                                        \
        }                                                                            \
    }

    // One chunk (12 kk): 4 MMAs/kk over 4 acc chains; W from pair-buffer P, parity par.
    #define MMA_CHUNK(ACC, P)                                                        \
    {                                                                                \
        const char* wch = smem + SM_WB + (P) * WPAIR + par * WCHUNK;                 \
        _Pragma("unroll")                                                            \
        for (int z = 0; z < 16; z++) (ACC)[z] = 0.0f;                                \
        uint4 nh0 = *(const uint4*)(wch + lane * 16);                                \
        uint4 nh1 = *(const uint4*)(wch + 512 + lane * 16);                          \
        _Pragma("unroll")                                                            \
        for (int kk = 0; kk < 12; kk++) {                                            \
            uint4 ch0 = nh0, ch1 = nh1;                                              \
            if (kk < 11) {                                                           \
                int kn = kk + 1;                                                     \
                int o = (kn >= 6) * 6144 + (kn - (kn >= 6) * 6) * 1024 + lane * 16;  \
                nh0 = *(const uint4*)(wch + o);                                      \
                nh1 = *(const uint4*)(wch + o + 512);                                \
            }                                                                        \
            mma16816h((ACC) + 0,  AH[kk], ch0.x, ch0.y);                             \
            mma16816h((ACC) + 4,  AH[kk], ch0.z, ch0.w);                             \
            mma16816h((ACC) + 8,  AH[kk], ch1.x, ch1.y);                             \
            mma16816h((ACC) + 12, AH[kk], ch1.z, ch1.w);                             \
        }                                                                            \
    }

    // Prefetch chunk pair R (chunks 2R, 2R+1; 24576B) into pair-buffer R&1: 96B/thread
    #define PREFETCH_PAIR(R)                                                         \
    {                                                                                \
        uint32_t dst = sbase + SM_WB + ((R) & 1) * WPAIR;                            \
        const char* srcW = (const char*)g_WF + (R) * WPAIR;                          \
        _Pragma("unroll")                                                            \
        for (int i = 0; i < 6; i++) {                                                \
            int o = tid * 16 + i * 4096;                                             \
            cpasync16(dst + o, srcW + o);                                            \
        }                                                                            \
        CP_COMMIT();                                                                 \
    }

    for (int t = 0; t < T_STEPS; t++) {
        const int act = mask[(size_t)t * N_NODES + node];

        // emb rebuild: pair-split k-ranges, packed fp16 stores
        {
            float2 xy = ((const float2*)nodes)[(size_t)t * N_NODES + base + erow];
            #pragma unroll 4
            for (int i = 0; i < 8; i++) {
                int k = ek0 + 2 * i;
                float e0 = fmaxf(fmaf(xy.x, We[k], fmaf(xy.y, We[64 + k], be[k])), 0.0f);
                float e1 = fmaxf(fmaf(xy.x, We[k + 1], fmaf(xy.y, We[64 + k + 1], be[k + 1])), 0.0f);
                uint32_t pk = (uint32_t)__half_as_ushort(__float2half_rn(e0))
                            | ((uint32_t)__half_as_ushort(__float2half_rn(e1)) << 16);
                *(uint32_t*)(smem + SM_XH + erow * XPITCH + 2 * k) = pk;
            }
        }
        __syncthreads();   // emb (pair-written) + last step's h writes visible

        PREFETCH_PAIR(0)

        // load A fragments once per step (register-resident X, single fp16)
        uint32_t AH[12][4];
        #pragma unroll
        for (int kk = 0; kk < 12; kk++)
            ldsm4(AH[kk][0], AH[kk][1], AH[kk][2], AH[kk][3], xhBase + aoff + kk * 32);

        float oacc[5] = {0.f, 0.f, 0.f, 0.f, 0.f};
        float accA[16], accB[16];

        // 8 rounds; warp handles chunk 2r+par; epilogue(prev) under MMA(cur)
        for (int r2 = 0; r2 < 8; r2 += 2) {
            CP_WAIT0();
            __syncthreads();
            if (r2 + 1 < 8) PREFETCH_PAIR(r2 + 1)
            MMA_CHUNK(accA, 0)
            if (r2 > 0) EPILOGUE(accB, 2 * (r2 - 1) + par)
            CP_WAIT0();
            __syncthreads();
            if (r2 + 2 < 8) PREFETCH_PAIR(r2 + 2)
            MMA_CHUNK(accB, 1)
            EPILOGUE(accA, 2 * r2 + par)
        }
        EPILOGUE(accB, 14 + par)

        // per-warp j-pair combine, stash partial per (row, parity)
        float comb[5];
        #pragma unroll
        for (int z = 0; z < 5; z++)
            comb[z] = oacc[z] + __shfl_xor_sync(0xffffffffu, oacc[z], 2);
        if (p4 < 2) {
            float* s = sOutP + (row * 2 + par) * 5;
            s[0] = comb[0]; s[1] = comb[1]; s[2] = comb[2]; s[3] = comb[3]; s[4] = comb[4];
        }
        __syncthreads();

        // combine parities and write out (one thread per row)
        if (tid < TILE_N) {
            int a2 = mask[(size_t)t * N_NODES + base + tid];
            float* op = out + ((size_t)t * N_NODES + base + tid) * 5;
            if (a2) {
                float* pa = sOutP + tid * 10;
                op[0] = pa[0] + pa[5] + bout[0];
                op[1] = pa[1] + pa[6] + bout[1];
                op[2] = pa[2] + pa[7] + bout[2];
                op[3] = pa[3] + pa[8] + bout[3];
                op[4] = pa[4] + pa[9] + bout[4];
            } else {
                op[0] = 0.f; op[1] = 0.f; op[2] = 0.f; op[3] = 0.f; op[4] = 0.f;
            }
        }
        __syncthreads();
    }

    // ---- final h (exact hi+lo), c ----
    for (int idx = tid; idx < TILE_N * DH; idx += NTHREADS) {
        int n = idx >> 7, j = idx & 127;
        float hv = __half2float(__ushort_as_half(
                       *(unsigned short*)(smem + SM_XH + n * XPITCH + 128 + 2 * j)))
                 + __half2float(__ushort_as_half(g_HL[(size_t)(base + n) * DH + j]));
        hfin[(size_t)(base + n) * DH + j] = hv;
        cfin[(size_t)(base + n) * DH + j] = sc[n * CPITCH + j];
    }
}

extern "C" void kernel_launch(void* const* d_in, const int* in_sizes, int n_in,
                              void* d_out, int out_size) {
    const float* nodes = (const float*)d_in[0];
    const int* mask    = (const int*)d_in[1];
    const float* h0    = (const float*)d_in[2];
    const float* c0    = (const float*)d_in[3];
    const float* We    = (const float*)d_in[4];
    const float* be    = (const float*)d_in[5];
    const float* Wih   = (const float*)d_in[6];
    const float* bih   = (const float*)d_in[7];
    const float* Whh   = (const float*)d_in[8];
    const float* bhh   = (const float*)d_in[9];
    const float* Wout  = (const float*)d_in[10];
    const float* bout  = (const float*)d_in[11];

    float* out  = (float*)d_out;
    float* hfin = out + (size_t)T_STEPS * N_NODES * 5;
    float* cfin = hfin + (size_t)N_NODES * DH;

    prep_frag<<<(32 * 6 * 2 * 32 * 4 + 255) / 256, 256>>>(Wih, Whh);

    cudaFuncSetAttribute(vlstm_mma, cudaFuncAttributeMaxDynamicSharedMemorySize, SMEM_TOTAL);
    vlstm_mma<<<NBLOCKS, NTHREADS, SMEM_TOTAL>>>(
        nodes, mask, h0, c0, We, be, bih, bhh, Wout, bout, out, hfin, cfin);
}